// round 8
// baseline (speedup 1.0000x reference)
#include <cuda_runtime.h>
#include <cuda_bf16.h>
#include <cstdint>

// out[i] = cos(x[i]) * cos(params[(i % 1024) * 3])
// x: 8*8192*1024 fp32 = 256MB; params: [16,64,3].
//
// Double-buffered TMA bulk stream, 32KB tiles: each CTA owns TWO
// consecutive 32KB tiles; both bulk loads issued immediately; compute
// in-place in smem; bulk-store each tile when ready. grid=4096,
// 64KB payload smem -> 3 CTAs/SM.
//
// Tile = 8192 floats = 8 channel-blocks of 1024 -> float4 channel group
// of (tid + i*256) within any tile == tid -> ry in 4 registers.

#define THREADS 256
#define TILE_BYTES 32768
#define TILE_F4    (TILE_BYTES / 16)   // 2048
#define PER_THREAD (TILE_F4 / THREADS) // 8

__device__ __forceinline__ uint32_t smem_u32(const void* p) {
    uint64_t t;
    asm("cvta.to.shared.u64 %0, %1;" : "=l"(t) : "l"(p));
    return (uint32_t)t;
}

__device__ __forceinline__ void mbar_wait0(uint32_t mbar) {
    uint32_t done;
    asm volatile(
        "{\n\t.reg .pred p;\n\t"
        "mbarrier.try_wait.parity.acquire.cta.shared::cta.b64 p, [%1], 0;\n\t"
        "selp.b32 %0, 1, 0, p;\n\t}"
        : "=r"(done) : "r"(mbar) : "memory");
    if (!done) {
        asm volatile(
            "{\n\t.reg .pred P1;\n\t"
            "WL_%=:\n\t"
            "mbarrier.try_wait.parity.acquire.cta.shared::cta.b64 P1, [%0], 0, 0x989680;\n\t"
            "@P1 bra.uni WD_%=;\n\t"
            "bra.uni WL_%=;\n\t"
            "WD_%=:\n\t}"
            :: "r"(mbar) : "memory");
    }
}

__global__ __launch_bounds__(THREADS)
void qa_bulk32_kernel(const float* __restrict__ x,
                      const float* __restrict__ params,
                      float* __restrict__ out)
{
    __shared__ __align__(128) float4 s_buf[2][TILE_F4];
    __shared__ __align__(8) uint64_t mbar[2];

    const int tid = threadIdx.x;

    // Per-thread ry (channel group == tid within every tile).
    const int c = tid * 4;
    float4 r;
    r.x = cosf(params[(c + 0) * 3]);
    r.y = cosf(params[(c + 1) * 3]);
    r.z = cosf(params[(c + 2) * 3]);
    r.w = cosf(params[(c + 3) * 3]);

    const uint32_t mb0 = smem_u32(&mbar[0]);
    const uint32_t mb1 = smem_u32(&mbar[1]);
    const uint32_t sb0 = smem_u32(s_buf[0]);
    const uint32_t sb1 = smem_u32(s_buf[1]);

    const float* gsrc = x   + (size_t)blockIdx.x * 2 * (TILE_BYTES / 4);
    float*       gdst = out + (size_t)blockIdx.x * 2 * (TILE_BYTES / 4);

    if (tid == 0) {
        asm volatile("mbarrier.init.shared.b64 [%0], 1;" :: "r"(mb0) : "memory");
        asm volatile("mbarrier.init.shared.b64 [%0], 1;" :: "r"(mb1) : "memory");
    }
    __syncthreads();

    if (tid == 0) {
        // Issue BOTH 32KB bulk loads immediately.
        asm volatile("mbarrier.arrive.expect_tx.shared.b64 _, [%0], %1;"
                     :: "r"(mb0), "r"((uint32_t)TILE_BYTES) : "memory");
        asm volatile(
            "cp.async.bulk.shared::cta.global.mbarrier::complete_tx::bytes "
            "[%0], [%1], %2, [%3];"
            :: "r"(sb0), "l"(gsrc), "r"((uint32_t)TILE_BYTES), "r"(mb0)
            : "memory");
        asm volatile("mbarrier.arrive.expect_tx.shared.b64 _, [%0], %1;"
                     :: "r"(mb1), "r"((uint32_t)TILE_BYTES) : "memory");
        asm volatile(
            "cp.async.bulk.shared::cta.global.mbarrier::complete_tx::bytes "
            "[%0], [%1], %2, [%3];"
            :: "r"(sb1), "l"(gsrc + TILE_BYTES / 4), "r"((uint32_t)TILE_BYTES), "r"(mb1)
            : "memory");
    }

    // ---- Tile 0 ----
    mbar_wait0(mb0);
#pragma unroll
    for (int i = 0; i < PER_THREAD; i++) {
        float4 v = s_buf[0][tid + i * THREADS];
        float4 o;
        o.x = __cosf(v.x) * r.x;
        o.y = __cosf(v.y) * r.y;
        o.z = __cosf(v.z) * r.z;
        o.w = __cosf(v.w) * r.w;
        s_buf[0][tid + i * THREADS] = o;   // in-place
    }
    __syncthreads();
    if (tid == 0) {
        asm volatile("fence.proxy.async.shared::cta;" ::: "memory");
        asm volatile(
            "cp.async.bulk.global.shared::cta.bulk_group [%0], [%1], %2;"
            :: "l"(gdst), "r"(sb0), "r"((uint32_t)TILE_BYTES) : "memory");
        asm volatile("cp.async.bulk.commit_group;" ::: "memory");
    }

    // ---- Tile 1 ----
    mbar_wait0(mb1);
#pragma unroll
    for (int i = 0; i < PER_THREAD; i++) {
        float4 v = s_buf[1][tid + i * THREADS];
        float4 o;
        o.x = __cosf(v.x) * r.x;
        o.y = __cosf(v.y) * r.y;
        o.z = __cosf(v.z) * r.z;
        o.w = __cosf(v.w) * r.w;
        s_buf[1][tid + i * THREADS] = o;   // in-place
    }
    __syncthreads();
    if (tid == 0) {
        asm volatile("fence.proxy.async.shared::cta;" ::: "memory");
        asm volatile(
            "cp.async.bulk.global.shared::cta.bulk_group [%0], [%1], %2;"
            :: "l"(gdst + TILE_BYTES / 4), "r"(sb1), "r"((uint32_t)TILE_BYTES)
            : "memory");
        asm volatile("cp.async.bulk.commit_group;" ::: "memory");
        asm volatile("cp.async.bulk.wait_group.read 0;" ::: "memory");
    }
}

// Fallback for any tail elements (not expected for this shape).
__global__ void qa_tail_kernel(const float* __restrict__ x,
                               const float* __restrict__ params,
                               float* __restrict__ out,
                               int start, int n)
{
    int i = start + blockIdx.x * blockDim.x + threadIdx.x;
    if (i < n) {
        float ry = cosf(params[(i & 1023) * 3]);
        out[i] = __cosf(x[i]) * ry;
    }
}

extern "C" void kernel_launch(void* const* d_in, const int* in_sizes, int n_in,
                              void* d_out, int out_size)
{
    const float* x      = (const float*)d_in[0];
    const float* params = (const float*)d_in[1];
    float* out          = (float*)d_out;

    int n = in_sizes[0];                       // 67,108,864
    int floats_per_cta = 2 * TILE_BYTES / 4;   // 16384
    int nctas = n / floats_per_cta;            // 4096
    int covered = nctas * floats_per_cta;

    if (nctas > 0) {
        cudaFuncSetAttribute(qa_bulk32_kernel,
                             cudaFuncAttributePreferredSharedMemoryCarveout, 100);
        qa_bulk32_kernel<<<nctas, THREADS>>>(x, params, out);
    }

    int tail = n - covered;
    if (tail > 0) {
        int tb = 256;
        qa_tail_kernel<<<(tail + tb - 1) / tb, tb>>>(x, params, out, covered, n);
    }
}

// round 9
// speedup vs baseline: 1.0135x; 1.0135x over previous
#include <cuda_runtime.h>
#include <cuda_bf16.h>
#include <cstdint>

// out[i] = cos(x[i]) * cos(params[(i % 1024) * 3])
// x: 8*8192*1024 fp32 = 256MB; params: [16,64,3].
//
// Final config (measured best across 6 structural variants, all pinned at
// ~6.2-6.3 TB/s = platform mixed-stream ceiling):
// Double-buffered TMA bulk stream: each CTA owns TWO consecutive 16KB
// tiles; both bulk loads issued immediately (2x in-flight reads/CTA from
// cycle 0); compute in-place in smem; bulk-store each tile when ready.
// grid=8192, 33KB smem -> 6 CTAs/SM.
//
// Tile = 4096 floats = 4 channel-blocks of 1024 -> float4 channel group
// of (tid + i*256) within any tile == tid -> ry lives in 4 registers.

#define THREADS 256
#define TILE_BYTES 16384
#define TILE_F4    (TILE_BYTES / 16)   // 1024
#define PER_THREAD (TILE_F4 / THREADS) // 4

__device__ __forceinline__ uint32_t smem_u32(const void* p) {
    uint64_t t;
    asm("cvta.to.shared.u64 %0, %1;" : "=l"(t) : "l"(p));
    return (uint32_t)t;
}

__device__ __forceinline__ void mbar_wait0(uint32_t mbar) {
    uint32_t done;
    asm volatile(
        "{\n\t.reg .pred p;\n\t"
        "mbarrier.try_wait.parity.acquire.cta.shared::cta.b64 p, [%1], 0;\n\t"
        "selp.b32 %0, 1, 0, p;\n\t}"
        : "=r"(done) : "r"(mbar) : "memory");
    if (!done) {
        asm volatile(
            "{\n\t.reg .pred P1;\n\t"
            "WL_%=:\n\t"
            "mbarrier.try_wait.parity.acquire.cta.shared::cta.b64 P1, [%0], 0, 0x989680;\n\t"
            "@P1 bra.uni WD_%=;\n\t"
            "bra.uni WL_%=;\n\t"
            "WD_%=:\n\t}"
            :: "r"(mbar) : "memory");
    }
}

__global__ __launch_bounds__(THREADS)
void qa_bulk2_kernel(const float* __restrict__ x,
                     const float* __restrict__ params,
                     float* __restrict__ out)
{
    __shared__ __align__(128) float4 s_buf[2][TILE_F4];
    __shared__ __align__(8) uint64_t mbar[2];

    const int tid = threadIdx.x;

    // Per-thread ry (channel group == tid within every tile).
    const int c = tid * 4;
    float4 r;
    r.x = cosf(params[(c + 0) * 3]);
    r.y = cosf(params[(c + 1) * 3]);
    r.z = cosf(params[(c + 2) * 3]);
    r.w = cosf(params[(c + 3) * 3]);

    const uint32_t mb0 = smem_u32(&mbar[0]);
    const uint32_t mb1 = smem_u32(&mbar[1]);
    const uint32_t sb0 = smem_u32(s_buf[0]);
    const uint32_t sb1 = smem_u32(s_buf[1]);

    const float* gsrc = x   + (size_t)blockIdx.x * 2 * (TILE_BYTES / 4);
    float*       gdst = out + (size_t)blockIdx.x * 2 * (TILE_BYTES / 4);

    if (tid == 0) {
        asm volatile("mbarrier.init.shared.b64 [%0], 1;" :: "r"(mb0) : "memory");
        asm volatile("mbarrier.init.shared.b64 [%0], 1;" :: "r"(mb1) : "memory");
    }
    __syncthreads();

    if (tid == 0) {
        // Issue BOTH 16KB bulk loads immediately.
        asm volatile("mbarrier.arrive.expect_tx.shared.b64 _, [%0], %1;"
                     :: "r"(mb0), "r"((uint32_t)TILE_BYTES) : "memory");
        asm volatile(
            "cp.async.bulk.shared::cta.global.mbarrier::complete_tx::bytes "
            "[%0], [%1], %2, [%3];"
            :: "r"(sb0), "l"(gsrc), "r"((uint32_t)TILE_BYTES), "r"(mb0)
            : "memory");
        asm volatile("mbarrier.arrive.expect_tx.shared.b64 _, [%0], %1;"
                     :: "r"(mb1), "r"((uint32_t)TILE_BYTES) : "memory");
        asm volatile(
            "cp.async.bulk.shared::cta.global.mbarrier::complete_tx::bytes "
            "[%0], [%1], %2, [%3];"
            :: "r"(sb1), "l"(gsrc + TILE_BYTES / 4), "r"((uint32_t)TILE_BYTES), "r"(mb1)
            : "memory");
    }

    // ---- Tile 0 ----
    mbar_wait0(mb0);
#pragma unroll
    for (int i = 0; i < PER_THREAD; i++) {
        float4 v = s_buf[0][tid + i * THREADS];
        float4 o;
        o.x = __cosf(v.x) * r.x;
        o.y = __cosf(v.y) * r.y;
        o.z = __cosf(v.z) * r.z;
        o.w = __cosf(v.w) * r.w;
        s_buf[0][tid + i * THREADS] = o;   // in-place
    }
    __syncthreads();
    if (tid == 0) {
        asm volatile("fence.proxy.async.shared::cta;" ::: "memory");
        asm volatile(
            "cp.async.bulk.global.shared::cta.bulk_group [%0], [%1], %2;"
            :: "l"(gdst), "r"(sb0), "r"((uint32_t)TILE_BYTES) : "memory");
        asm volatile("cp.async.bulk.commit_group;" ::: "memory");
    }

    // ---- Tile 1 ----
    mbar_wait0(mb1);
#pragma unroll
    for (int i = 0; i < PER_THREAD; i++) {
        float4 v = s_buf[1][tid + i * THREADS];
        float4 o;
        o.x = __cosf(v.x) * r.x;
        o.y = __cosf(v.y) * r.y;
        o.z = __cosf(v.z) * r.z;
        o.w = __cosf(v.w) * r.w;
        s_buf[1][tid + i * THREADS] = o;   // in-place
    }
    __syncthreads();
    if (tid == 0) {
        asm volatile("fence.proxy.async.shared::cta;" ::: "memory");
        asm volatile(
            "cp.async.bulk.global.shared::cta.bulk_group [%0], [%1], %2;"
            :: "l"(gdst + TILE_BYTES / 4), "r"(sb1), "r"((uint32_t)TILE_BYTES)
            : "memory");
        asm volatile("cp.async.bulk.commit_group;" ::: "memory");
        // Only needed so smem isn't retired while the store still reads it.
        asm volatile("cp.async.bulk.wait_group.read 0;" ::: "memory");
    }
}

extern "C" void kernel_launch(void* const* d_in, const int* in_sizes, int n_in,
                              void* d_out, int out_size)
{
    const float* x      = (const float*)d_in[0];
    const float* params = (const float*)d_in[1];
    float* out          = (float*)d_out;

    int n = in_sizes[0];                       // 67,108,864
    int floats_per_cta = 2 * TILE_BYTES / 4;   // 8192
    int nctas = n / floats_per_cta;            // 8192 (shape divides exactly)

    qa_bulk2_kernel<<<nctas, THREADS>>>(x, params, out);
}

// round 10
// speedup vs baseline: 1.0217x; 1.0082x over previous
#include <cuda_runtime.h>
#include <cuda_bf16.h>
#include <cstdint>

// out[i] = cos(x[i]) * cos(params[(i % 1024) * 3])
// x: 8*8192*1024 fp32 = 256MB; params: [16,64,3].
//
// Double-buffered TMA bulk stream (measured-best config) + L2 evict_first
// cache policy on both bulk directions (zero-reuse stream).
// Each CTA: two consecutive 16KB tiles, both loads issued up front,
// compute in-place in smem, bulk-store when ready. grid=8192, 6 CTAs/SM.
//
// Tile = 4096 floats = 4 channel-blocks of 1024 -> float4 channel group
// of (tid + i*256) within any tile == tid -> ry lives in 4 registers.

#define THREADS 256
#define TILE_BYTES 16384
#define TILE_F4    (TILE_BYTES / 16)   // 1024
#define PER_THREAD (TILE_F4 / THREADS) // 4

__device__ __forceinline__ uint32_t smem_u32(const void* p) {
    uint64_t t;
    asm("cvta.to.shared.u64 %0, %1;" : "=l"(t) : "l"(p));
    return (uint32_t)t;
}

__device__ __forceinline__ uint64_t mk_evict_first_policy() {
    uint64_t pol;
    asm("createpolicy.fractional.L2::evict_first.b64 %0, 1.0;" : "=l"(pol));
    return pol;
}

__device__ __forceinline__ void bulk_load_g2s(uint32_t sdst, const void* gsrc,
                                              uint32_t bytes, uint32_t mbar,
                                              uint64_t pol) {
    asm volatile(
        "cp.async.bulk.shared::cta.global.mbarrier::complete_tx::bytes.L2::cache_hint "
        "[%0], [%1], %2, [%3], %4;"
        :: "r"(sdst), "l"(gsrc), "r"(bytes), "r"(mbar), "l"(pol)
        : "memory");
}

__device__ __forceinline__ void bulk_store_s2g(void* gdst, uint32_t ssrc,
                                               uint32_t bytes, uint64_t pol) {
    asm volatile(
        "cp.async.bulk.global.shared::cta.bulk_group.L2::cache_hint "
        "[%0], [%1], %2, %3;"
        :: "l"(gdst), "r"(ssrc), "r"(bytes), "l"(pol)
        : "memory");
}

__device__ __forceinline__ void mbar_wait0(uint32_t mbar) {
    uint32_t done;
    asm volatile(
        "{\n\t.reg .pred p;\n\t"
        "mbarrier.try_wait.parity.acquire.cta.shared::cta.b64 p, [%1], 0;\n\t"
        "selp.b32 %0, 1, 0, p;\n\t}"
        : "=r"(done) : "r"(mbar) : "memory");
    if (!done) {
        asm volatile(
            "{\n\t.reg .pred P1;\n\t"
            "WL_%=:\n\t"
            "mbarrier.try_wait.parity.acquire.cta.shared::cta.b64 P1, [%0], 0, 0x989680;\n\t"
            "@P1 bra.uni WD_%=;\n\t"
            "bra.uni WL_%=;\n\t"
            "WD_%=:\n\t}"
            :: "r"(mbar) : "memory");
    }
}

__global__ __launch_bounds__(THREADS)
void qa_bulk2_kernel(const float* __restrict__ x,
                     const float* __restrict__ params,
                     float* __restrict__ out)
{
    __shared__ __align__(128) float4 s_buf[2][TILE_F4];
    __shared__ __align__(8) uint64_t mbar[2];

    const int tid = threadIdx.x;

    // Per-thread ry (channel group == tid within every tile).
    const int c = tid * 4;
    float4 r;
    r.x = cosf(params[(c + 0) * 3]);
    r.y = cosf(params[(c + 1) * 3]);
    r.z = cosf(params[(c + 2) * 3]);
    r.w = cosf(params[(c + 3) * 3]);

    const uint32_t mb0 = smem_u32(&mbar[0]);
    const uint32_t mb1 = smem_u32(&mbar[1]);
    const uint32_t sb0 = smem_u32(s_buf[0]);
    const uint32_t sb1 = smem_u32(s_buf[1]);

    const float* gsrc = x   + (size_t)blockIdx.x * 2 * (TILE_BYTES / 4);
    float*       gdst = out + (size_t)blockIdx.x * 2 * (TILE_BYTES / 4);

    if (tid == 0) {
        asm volatile("mbarrier.init.shared.b64 [%0], 1;" :: "r"(mb0) : "memory");
        asm volatile("mbarrier.init.shared.b64 [%0], 1;" :: "r"(mb1) : "memory");
    }
    __syncthreads();

    if (tid == 0) {
        const uint64_t pol = mk_evict_first_policy();
        // Issue BOTH 16KB bulk loads immediately.
        asm volatile("mbarrier.arrive.expect_tx.shared.b64 _, [%0], %1;"
                     :: "r"(mb0), "r"((uint32_t)TILE_BYTES) : "memory");
        bulk_load_g2s(sb0, gsrc, TILE_BYTES, mb0, pol);
        asm volatile("mbarrier.arrive.expect_tx.shared.b64 _, [%0], %1;"
                     :: "r"(mb1), "r"((uint32_t)TILE_BYTES) : "memory");
        bulk_load_g2s(sb1, gsrc + TILE_BYTES / 4, TILE_BYTES, mb1, pol);
    }

    // ---- Tile 0 ----
    mbar_wait0(mb0);
#pragma unroll
    for (int i = 0; i < PER_THREAD; i++) {
        float4 v = s_buf[0][tid + i * THREADS];
        float4 o;
        o.x = __cosf(v.x) * r.x;
        o.y = __cosf(v.y) * r.y;
        o.z = __cosf(v.z) * r.z;
        o.w = __cosf(v.w) * r.w;
        s_buf[0][tid + i * THREADS] = o;   // in-place
    }
    __syncthreads();
    if (tid == 0) {
        const uint64_t pol = mk_evict_first_policy();
        asm volatile("fence.proxy.async.shared::cta;" ::: "memory");
        bulk_store_s2g(gdst, sb0, TILE_BYTES, pol);
        asm volatile("cp.async.bulk.commit_group;" ::: "memory");
    }

    // ---- Tile 1 ----
    mbar_wait0(mb1);
#pragma unroll
    for (int i = 0; i < PER_THREAD; i++) {
        float4 v = s_buf[1][tid + i * THREADS];
        float4 o;
        o.x = __cosf(v.x) * r.x;
        o.y = __cosf(v.y) * r.y;
        o.z = __cosf(v.z) * r.z;
        o.w = __cosf(v.w) * r.w;
        s_buf[1][tid + i * THREADS] = o;   // in-place
    }
    __syncthreads();
    if (tid == 0) {
        const uint64_t pol = mk_evict_first_policy();
        asm volatile("fence.proxy.async.shared::cta;" ::: "memory");
        bulk_store_s2g(gdst + TILE_BYTES / 4, sb1, TILE_BYTES, pol);
        asm volatile("cp.async.bulk.commit_group;" ::: "memory");
        // smem must stay live until the store has read it.
        asm volatile("cp.async.bulk.wait_group.read 0;" ::: "memory");
    }
}

extern "C" void kernel_launch(void* const* d_in, const int* in_sizes, int n_in,
                              void* d_out, int out_size)
{
    const float* x      = (const float*)d_in[0];
    const float* params = (const float*)d_in[1];
    float* out          = (float*)d_out;

    int n = in_sizes[0];                       // 67,108,864
    int floats_per_cta = 2 * TILE_BYTES / 4;   // 8192
    int nctas = n / floats_per_cta;            // 8192 (shape divides exactly)

    qa_bulk2_kernel<<<nctas, THREADS>>>(x, params, out);
}